// round 3
// baseline (speedup 1.0000x reference)
#include <cuda_runtime.h>

// B=16, mask (16,2,512,512) -bilinear x2-> (16,2,1024,1024)
// fused = x_mask*xl + y_mask*yl (3 ch), out = relu(conv1x1(fused)+b)
// d_out: out (48 planes) | x_mask (16 planes) | y_mask (16 planes), plane=1024*1024
//
// Each thread: 2 float4 groups in the same row, 512 floats apart.
// Warp lanes cover consecutive float4s -> every LDG/STG is 512B contiguous.

#define HS 512
#define WS 512
#define HU 1024
#define WU 1024

__global__ __launch_bounds__(256)
void fused_upsample_blend_conv2(const float* __restrict__ mask,
                                const float* __restrict__ xl,
                                const float* __restrict__ yl,
                                const float* __restrict__ cw,
                                const float* __restrict__ cb,
                                float* __restrict__ out)
{
    const int idx = blockIdx.x * blockDim.x + threadIdx.x;
    // idx -> (b, h, w4): w4 in [0,128), h in [0,1024), b in [0,16)
    const int w4 = idx & 127;
    const int h  = (idx >> 7) & 1023;
    const int b  = idx >> 17;

    // vertical source rows (half-pixel bilinear, scale 2):
    // even h=2j: 0.75*row[j]+0.25*row[j-1]; odd h=2j+1: 0.75*row[j]+0.25*row[j+1]
    const int hj = h >> 1;
    const int r1 = hj;
    const int r2 = (h & 1) ? min(hj + 1, HS - 1) : max(hj - 1, 0);

    const float* m0r1 = mask + (((long)b * 2 + 0) * HS + r1) * WS;
    const float* m0r2 = mask + (((long)b * 2 + 0) * HS + r2) * WS;
    const float* m1r1 = mask + (((long)b * 2 + 1) * HS + r1) * WS;
    const float* m1r2 = mask + (((long)b * 2 + 1) * HS + r2) * WS;

    // two groups of 4 output pixels: wA = 4*w4, wB = wA + 512
    const int jA = w4 << 1;          // source col base for group A (0..254)
    const int jB = jA + 256;         // group B (256..510)
    const int aM1 = max(jA - 1, 0);  // only w4==0 clamps
    const int aP2 = jA + 2;          // <=256, no clamp
    const int bM1 = jB - 1;          // >=255, no clamp
    const int bP2 = min(jB + 2, WS - 1);  // only w4==127 clamps

    // ---- kick off the 12 big streaming loads first (maximize MLP) ----
    const int wA = w4 << 2;
    const long plane = (long)HU * WU;
    const long pixA  = (long)h * WU + wA;
    const long pixB  = pixA + 512;
    const float* xb = xl + (long)b * 3 * plane;
    const float* yb = yl + (long)b * 3 * plane;

    const float4 xA0 = __ldcs((const float4*)(xb + 0 * plane + pixA));
    const float4 xA1 = __ldcs((const float4*)(xb + 1 * plane + pixA));
    const float4 xA2 = __ldcs((const float4*)(xb + 2 * plane + pixA));
    const float4 yA0 = __ldcs((const float4*)(yb + 0 * plane + pixA));
    const float4 yA1 = __ldcs((const float4*)(yb + 1 * plane + pixA));
    const float4 yA2 = __ldcs((const float4*)(yb + 2 * plane + pixA));
    const float4 xB0 = __ldcs((const float4*)(xb + 0 * plane + pixB));
    const float4 xB1 = __ldcs((const float4*)(xb + 1 * plane + pixB));
    const float4 xB2 = __ldcs((const float4*)(xb + 2 * plane + pixB));
    const float4 yB0 = __ldcs((const float4*)(yb + 0 * plane + pixB));
    const float4 yB1 = __ldcs((const float4*)(yb + 1 * plane + pixB));
    const float4 yB2 = __ldcs((const float4*)(yb + 2 * plane + pixB));

    // ---- mask vertical interp (L1-resident scalar loads) ----
    #define VERT(R1, R2, C) (0.75f * __ldg((R1) + (C)) + 0.25f * __ldg((R2) + (C)))
    // ch0 group A/B
    const float a00 = VERT(m0r1, m0r2, aM1), a01 = VERT(m0r1, m0r2, jA);
    const float a02 = VERT(m0r1, m0r2, jA + 1), a03 = VERT(m0r1, m0r2, aP2);
    const float b00 = VERT(m0r1, m0r2, bM1), b01 = VERT(m0r1, m0r2, jB);
    const float b02 = VERT(m0r1, m0r2, jB + 1), b03 = VERT(m0r1, m0r2, bP2);
    // ch1 group A/B
    const float a10 = VERT(m1r1, m1r2, aM1), a11 = VERT(m1r1, m1r2, jA);
    const float a12 = VERT(m1r1, m1r2, jA + 1), a13 = VERT(m1r1, m1r2, aP2);
    const float b10 = VERT(m1r1, m1r2, bM1), b11 = VERT(m1r1, m1r2, jB);
    const float b12 = VERT(m1r1, m1r2, jB + 1), b13 = VERT(m1r1, m1r2, bP2);
    #undef VERT

    // horizontal: out 2k -> .75 v[k] + .25 v[k-1]; out 2k+1 -> .75 v[k] + .25 v[k+1]
    #define HORIZ(d, v0, v1, v2, v3) \
        d.x = 0.75f * v1 + 0.25f * v0; d.y = 0.75f * v1 + 0.25f * v2; \
        d.z = 0.75f * v2 + 0.25f * v1; d.w = 0.75f * v2 + 0.25f * v3;
    float4 xmA, ymA, xmB, ymB;
    HORIZ(xmA, a00, a01, a02, a03)
    HORIZ(ymA, a10, a11, a12, a13)
    HORIZ(xmB, b00, b01, b02, b03)
    HORIZ(ymB, b10, b11, b12, b13)
    #undef HORIZ

    // conv params (uniform, L1 broadcast)
    const float w00 = __ldg(cw + 0), w01 = __ldg(cw + 1), w02 = __ldg(cw + 2);
    const float w10 = __ldg(cw + 3), w11 = __ldg(cw + 4), w12 = __ldg(cw + 5);
    const float w20 = __ldg(cw + 6), w21 = __ldg(cw + 7), w22 = __ldg(cw + 8);
    const float bb0 = __ldg(cb + 0), bb1 = __ldg(cb + 1), bb2 = __ldg(cb + 2);

    float* ob = out + (long)b * 3 * plane;
    const long XM_OFF = 48L * plane;
    const long YM_OFF = 64L * plane;

    // ---- group processing macro: fuse + conv + relu + store ----
    #define PROC(XM, YM, X0, X1, X2, Y0, Y1, Y2, PIX)                          \
    {                                                                          \
        float4 f0, f1, f2, o0, o1, o2;                                         \
        f0.x = XM.x * X0.x + YM.x * Y0.x; f0.y = XM.y * X0.y + YM.y * Y0.y;    \
        f0.z = XM.z * X0.z + YM.z * Y0.z; f0.w = XM.w * X0.w + YM.w * Y0.w;    \
        f1.x = XM.x * X1.x + YM.x * Y1.x; f1.y = XM.y * X1.y + YM.y * Y1.y;    \
        f1.z = XM.z * X1.z + YM.z * Y1.z; f1.w = XM.w * X1.w + YM.w * Y1.w;    \
        f2.x = XM.x * X2.x + YM.x * Y2.x; f2.y = XM.y * X2.y + YM.y * Y2.y;    \
        f2.z = XM.z * X2.z + YM.z * Y2.z; f2.w = XM.w * X2.w + YM.w * Y2.w;    \
        o0.x = fmaxf(w00 * f0.x + w01 * f1.x + w02 * f2.x + bb0, 0.f);         \
        o0.y = fmaxf(w00 * f0.y + w01 * f1.y + w02 * f2.y + bb0, 0.f);         \
        o0.z = fmaxf(w00 * f0.z + w01 * f1.z + w02 * f2.z + bb0, 0.f);         \
        o0.w = fmaxf(w00 * f0.w + w01 * f1.w + w02 * f2.w + bb0, 0.f);         \
        o1.x = fmaxf(w10 * f0.x + w11 * f1.x + w12 * f2.x + bb1, 0.f);         \
        o1.y = fmaxf(w10 * f0.y + w11 * f1.y + w12 * f2.y + bb1, 0.f);         \
        o1.z = fmaxf(w10 * f0.z + w11 * f1.z + w12 * f2.z + bb1, 0.f);         \
        o1.w = fmaxf(w10 * f0.w + w11 * f1.w + w12 * f2.w + bb1, 0.f);         \
        o2.x = fmaxf(w20 * f0.x + w21 * f1.x + w22 * f2.x + bb2, 0.f);         \
        o2.y = fmaxf(w20 * f0.y + w21 * f1.y + w22 * f2.y + bb2, 0.f);         \
        o2.z = fmaxf(w20 * f0.z + w21 * f1.z + w22 * f2.z + bb2, 0.f);         \
        o2.w = fmaxf(w20 * f0.w + w21 * f1.w + w22 * f2.w + bb2, 0.f);         \
        __stcs((float4*)(ob + 0 * plane + PIX), o0);                           \
        __stcs((float4*)(ob + 1 * plane + PIX), o1);                           \
        __stcs((float4*)(ob + 2 * plane + PIX), o2);                           \
        __stcs((float4*)(out + XM_OFF + (long)b * plane + PIX), XM);           \
        __stcs((float4*)(out + YM_OFF + (long)b * plane + PIX), YM);           \
    }

    PROC(xmA, ymA, xA0, xA1, xA2, yA0, yA1, yA2, pixA)
    PROC(xmB, ymB, xB0, xB1, xB2, yB0, yB1, yB2, pixB)
    #undef PROC
}

extern "C" void kernel_launch(void* const* d_in, const int* in_sizes, int n_in,
                              void* d_out, int out_size)
{
    const float* mask = (const float*)d_in[0];
    const float* xl   = (const float*)d_in[1];
    const float* yl   = (const float*)d_in[2];
    const float* cw   = (const float*)d_in[3];
    const float* cb   = (const float*)d_in[4];
    float* out = (float*)d_out;

    // 16 * 1024 * 128 threads, 256/block -> 8192 blocks
    const int total = 16 * 1024 * 128;
    fused_upsample_blend_conv2<<<total / 256, 256>>>(mask, xl, yl, cw, cb, out);
}

// round 4
// speedup vs baseline: 1.0194x; 1.0194x over previous
#include <cuda_runtime.h>

// B=16, mask (16,2,512,512) -bilinear x2-> (16,2,1024,1024)
// fused = x_mask*xl + y_mask*yl (3 ch), out = relu(conv1x1(fused)+b)
// d_out: out (48 planes) | x_mask (16 planes) | y_mask (16 planes), plane=1024*1024
//
// One float4 group (4 output pixels) per thread. Warp lanes cover consecutive
// float4s -> every LDG/STG is a fully coalesced 512B transaction.
// R3 lesson: keep regs low / occupancy high; 6 outstanding LDG.128 per thread
// is enough MLP. Streaming cache hints on the one-touch data.

#define HS 512
#define WS 512
#define HU 1024
#define WU 1024

__global__ __launch_bounds__(256, 6)
void fused_upsample_blend_conv(const float* __restrict__ mask,
                               const float* __restrict__ xl,
                               const float* __restrict__ yl,
                               const float* __restrict__ cw,
                               const float* __restrict__ cb,
                               float* __restrict__ out)
{
    const int idx = blockIdx.x * blockDim.x + threadIdx.x;
    // idx -> (b, h, w4): w4 in [0,256), h in [0,1024), b in [0,16)
    const int w4 = idx & 255;
    const int h  = (idx >> 8) & 1023;
    const int b  = idx >> 18;

    // ---- kick off the 6 big streaming loads first ----
    const int w = w4 << 2;
    const long plane = (long)HU * WU;
    const long pix   = (long)h * WU + w;
    const float* xb = xl + (long)b * 3 * plane;
    const float* yb = yl + (long)b * 3 * plane;

    const float4 a0 = __ldcs((const float4*)(xb + 0 * plane + pix));
    const float4 a1 = __ldcs((const float4*)(xb + 1 * plane + pix));
    const float4 a2 = __ldcs((const float4*)(xb + 2 * plane + pix));
    const float4 g0 = __ldcs((const float4*)(yb + 0 * plane + pix));
    const float4 g1 = __ldcs((const float4*)(yb + 1 * plane + pix));
    const float4 g2 = __ldcs((const float4*)(yb + 2 * plane + pix));

    // ---- bilinear mask upsample (half-pixel centers, scale 2) ----
    // out row h samples source row 0.5h-0.25:
    //   even h=2j: 0.75*row[j] + 0.25*row[j-1] (clamped)
    //   odd  h=2j+1: 0.75*row[j] + 0.25*row[j+1] (clamped)
    const int hj = h >> 1;
    const int r1 = hj;
    const int r2 = (h & 1) ? min(hj + 1, HS - 1) : max(hj - 1, 0);

    const int k0  = w4 << 1;              // 0..510
    const int cm1 = max(k0 - 1, 0);
    const int c1  = k0 + 1;
    const int cp2 = min(k0 + 2, WS - 1);

    const float* m0r1 = mask + (((long)b * 2 + 0) * HS + r1) * WS;
    const float* m0r2 = mask + (((long)b * 2 + 0) * HS + r2) * WS;
    const float* m1r1 = mask + (((long)b * 2 + 1) * HS + r1) * WS;
    const float* m1r2 = mask + (((long)b * 2 + 1) * HS + r2) * WS;

    // vertical interp at 4 source columns, both mask channels (L1/L2-resident)
    const float v0a = 0.75f * __ldg(m0r1 + cm1) + 0.25f * __ldg(m0r2 + cm1);
    const float v0b = 0.75f * __ldg(m0r1 + k0 ) + 0.25f * __ldg(m0r2 + k0 );
    const float v0c = 0.75f * __ldg(m0r1 + c1 ) + 0.25f * __ldg(m0r2 + c1 );
    const float v0d = 0.75f * __ldg(m0r1 + cp2) + 0.25f * __ldg(m0r2 + cp2);

    const float v1a = 0.75f * __ldg(m1r1 + cm1) + 0.25f * __ldg(m1r2 + cm1);
    const float v1b = 0.75f * __ldg(m1r1 + k0 ) + 0.25f * __ldg(m1r2 + k0 );
    const float v1c = 0.75f * __ldg(m1r1 + c1 ) + 0.25f * __ldg(m1r2 + c1 );
    const float v1d = 0.75f * __ldg(m1r1 + cp2) + 0.25f * __ldg(m1r2 + cp2);

    // horizontal: out 2k -> .75 v[k] + .25 v[k-1]; out 2k+1 -> .75 v[k] + .25 v[k+1]
    float4 xm, ym;
    xm.x = 0.75f * v0b + 0.25f * v0a;
    xm.y = 0.75f * v0b + 0.25f * v0c;
    xm.z = 0.75f * v0c + 0.25f * v0b;
    xm.w = 0.75f * v0c + 0.25f * v0d;

    ym.x = 0.75f * v1b + 0.25f * v1a;
    ym.y = 0.75f * v1b + 0.25f * v1c;
    ym.z = 0.75f * v1c + 0.25f * v1b;
    ym.w = 0.75f * v1c + 0.25f * v1d;

    // ---- fuse ----
    float4 f0, f1, f2;
    f0.x = xm.x * a0.x + ym.x * g0.x;  f0.y = xm.y * a0.y + ym.y * g0.y;
    f0.z = xm.z * a0.z + ym.z * g0.z;  f0.w = xm.w * a0.w + ym.w * g0.w;
    f1.x = xm.x * a1.x + ym.x * g1.x;  f1.y = xm.y * a1.y + ym.y * g1.y;
    f1.z = xm.z * a1.z + ym.z * g1.z;  f1.w = xm.w * a1.w + ym.w * g1.w;
    f2.x = xm.x * a2.x + ym.x * g2.x;  f2.y = xm.y * a2.y + ym.y * g2.y;
    f2.z = xm.z * a2.z + ym.z * g2.z;  f2.w = xm.w * a2.w + ym.w * g2.w;

    // conv params (uniform broadcast loads)
    const float w00 = __ldg(cw + 0), w01 = __ldg(cw + 1), w02 = __ldg(cw + 2);
    const float w10 = __ldg(cw + 3), w11 = __ldg(cw + 4), w12 = __ldg(cw + 5);
    const float w20 = __ldg(cw + 6), w21 = __ldg(cw + 7), w22 = __ldg(cw + 8);
    const float bb0 = __ldg(cb + 0), bb1 = __ldg(cb + 1), bb2 = __ldg(cb + 2);

    float4 o0, o1, o2;
    o0.x = fmaxf(w00 * f0.x + w01 * f1.x + w02 * f2.x + bb0, 0.f);
    o0.y = fmaxf(w00 * f0.y + w01 * f1.y + w02 * f2.y + bb0, 0.f);
    o0.z = fmaxf(w00 * f0.z + w01 * f1.z + w02 * f2.z + bb0, 0.f);
    o0.w = fmaxf(w00 * f0.w + w01 * f1.w + w02 * f2.w + bb0, 0.f);

    o1.x = fmaxf(w10 * f0.x + w11 * f1.x + w12 * f2.x + bb1, 0.f);
    o1.y = fmaxf(w10 * f0.y + w11 * f1.y + w12 * f2.y + bb1, 0.f);
    o1.z = fmaxf(w10 * f0.z + w11 * f1.z + w12 * f2.z + bb1, 0.f);
    o1.w = fmaxf(w10 * f0.w + w11 * f1.w + w12 * f2.w + bb1, 0.f);

    o2.x = fmaxf(w20 * f0.x + w21 * f1.x + w22 * f2.x + bb2, 0.f);
    o2.y = fmaxf(w20 * f0.y + w21 * f1.y + w22 * f2.y + bb2, 0.f);
    o2.z = fmaxf(w20 * f0.z + w21 * f1.z + w22 * f2.z + bb2, 0.f);
    o2.w = fmaxf(w20 * f0.w + w21 * f1.w + w22 * f2.w + bb2, 0.f);

    // ---- streaming stores ----
    float* ob = out + (long)b * 3 * plane;
    const long XM_OFF = 48L * plane;
    const long YM_OFF = 64L * plane;

    __stcs((float4*)(ob + 0 * plane + pix), o0);
    __stcs((float4*)(ob + 1 * plane + pix), o1);
    __stcs((float4*)(ob + 2 * plane + pix), o2);
    __stcs((float4*)(out + XM_OFF + (long)b * plane + pix), xm);
    __stcs((float4*)(out + YM_OFF + (long)b * plane + pix), ym);
}

extern "C" void kernel_launch(void* const* d_in, const int* in_sizes, int n_in,
                              void* d_out, int out_size)
{
    const float* mask = (const float*)d_in[0];
    const float* xl   = (const float*)d_in[1];
    const float* yl   = (const float*)d_in[2];
    const float* cw   = (const float*)d_in[3];
    const float* cb   = (const float*)d_in[4];
    float* out = (float*)d_out;

    // 16 * 1024 * 256 threads total, 256 per block -> 16384 blocks
    const int total = 16 * 1024 * 256;
    fused_upsample_blend_conv<<<total / 256, 256>>>(mask, xl, yl, cw, cb, out);
}